// round 1
// baseline (speedup 1.0000x reference)
#include <cuda_runtime.h>
#include <mma.h>
#include <cstdint>

using namespace nvcuda;

// Problem constants (fixed shapes)
#define N_NODES  50000
#define N_EDGES  1600000
#define N_GRAPHS 64
#define D_IN     128
#define D_H      512
#define D_OUT    16

// ---------------- device scratch (no allocation allowed) ----------------
__device__ float g_s1[(size_t)N_NODES * D_IN];   // 25.6 MB
__device__ float g_s2[(size_t)N_NODES * D_IN];   // 25.6 MB
__device__ int   g_deg[N_NODES];
__device__ float g_invdeg[N_NODES];
__device__ float g_gsum[N_GRAPHS * D_H];
__device__ int   g_gcnt[N_GRAPHS];
__device__ float g_pool2[N_GRAPHS * D_H];

// ---------------- kernels ----------------

__global__ void k_zero() {
    int i = blockIdx.x * blockDim.x + threadIdx.x;
    if (i < N_NODES) g_deg[i] = 0;
    if (i < N_GRAPHS * D_H) g_gsum[i] = 0.0f;
    if (i < N_GRAPHS) g_gcnt[i] = 0;
}

__global__ void k_deg(const int* __restrict__ rows) {
    int e = blockIdx.x * blockDim.x + threadIdx.x;
    if (e < N_EDGES) atomicAdd(&g_deg[rows[e]], 1);
}

__global__ void k_invdeg() {
    int i = blockIdx.x * blockDim.x + threadIdx.x;
    if (i < N_NODES) g_invdeg[i] = 1.0f / (float)(g_deg[i] + 1);  // +1 self loop
}

__global__ void k_hist(const int* __restrict__ batch) {
    __shared__ int h[N_GRAPHS];
    if (threadIdx.x < N_GRAPHS) h[threadIdx.x] = 0;
    __syncthreads();
    for (int i = blockIdx.x * blockDim.x + threadIdx.x; i < N_NODES;
         i += gridDim.x * blockDim.x)
        atomicAdd(&h[batch[i]], 1);
    __syncthreads();
    if (threadIdx.x < N_GRAPHS) atomicAdd(&g_gcnt[threadIdx.x], h[threadIdx.x]);
}

// dst[i,:] = scale(i) * src[i,:]   (self-loop init; scale==nullptr -> 1)
__global__ void k_prep(float4* __restrict__ dst, const float4* __restrict__ src,
                       const float* __restrict__ scale) {
    const int total = N_NODES * (D_IN / 4);
    for (int i = blockIdx.x * blockDim.x + threadIdx.x; i < total;
         i += gridDim.x * blockDim.x) {
        int row = i >> 5;  // 32 float4 per row
        float s = scale ? __ldg(&scale[row]) : 1.0f;
        float4 v = __ldg(&src[i]);
        v.x *= s; v.y *= s; v.z *= s; v.w *= s;
        dst[i] = v;
    }
}

// one warp per edge: dst[row,:] += scale(col) * src[col,:]
__global__ void k_scatter(float* __restrict__ dst, const float* __restrict__ src,
                          const float* __restrict__ scale,
                          const int* __restrict__ rows, const int* __restrict__ cols) {
    int e = blockIdx.x * 8 + (threadIdx.x >> 5);
    if (e >= N_EDGES) return;
    int lane = threadIdx.x & 31;
    int r = __ldg(&rows[e]);
    int c = __ldg(&cols[e]);
    float s = scale ? __ldg(&scale[c]) : 1.0f;
    float4 v = __ldg(((const float4*)(src + (size_t)c * D_IN)) + lane);
    v.x *= s; v.y *= s; v.z *= s; v.w *= s;
    atomicAdd(((float4*)(dst + (size_t)r * D_IN)) + lane, v);
}

// C = relu( (A .* invdeg) @ w1 + b1 ), fused per-graph sum accumulation.
// Block tile: 64(M) x 64(N), K=128 fully resident in SMEM. tf32 wmma.
#define GEMM_SMEM_BYTES ((64 * 128 + 128 * 64 + 64 * 72 + 64) * 4)

__global__ void __launch_bounds__(256)
k_gemm_pool(const float* __restrict__ A, const float* __restrict__ invdeg,
            const float* __restrict__ w1, const float* __restrict__ b1,
            const int* __restrict__ batch) {
    extern __shared__ float sm[];
    float* As = sm;                 // [64][128]
    float* Bs = As + 64 * 128;      // [128][64]
    float* Cs = Bs + 128 * 64;      // [64][72]
    int*   bs = (int*)(Cs + 64 * 72);

    const int row0 = blockIdx.x * 64;
    const int col0 = blockIdx.y * 64;
    const int tid  = threadIdx.x;

    // load A tile (scaled by invdeg), zero-pad beyond N_NODES
    for (int i = tid; i < 64 * 32; i += 256) {  // float4 index
        int r = i >> 5, q = i & 31;
        int node = row0 + r;
        float4 v = make_float4(0.f, 0.f, 0.f, 0.f);
        if (node < N_NODES) {
            v = __ldg(((const float4*)(A + (size_t)node * D_IN)) + q);
            float s = __ldg(&invdeg[node]);
            v.x *= s; v.y *= s; v.z *= s; v.w *= s;
        }
        ((float4*)As)[i] = v;
    }
    // load B tile: w1[128][512] cols [col0, col0+64)
    for (int i = tid; i < 128 * 16; i += 256) {  // float4 index
        int r = i >> 4, q = i & 15;
        ((float4*)Bs)[i] = __ldg(((const float4*)(w1 + (size_t)r * D_H + col0)) + q);
    }
    if (tid < 64) {
        int node = row0 + tid;
        bs[tid] = (node < N_NODES) ? __ldg(&batch[node]) : -1;
    }
    __syncthreads();

    const int wid = tid >> 5;
    const int wm = wid & 3;    // row subtile 16*wm
    const int wn = wid >> 2;   // col slab 32*wn
    wmma::fragment<wmma::accumulator, 16, 16, 8, float> c0, c1;
    wmma::fill_fragment(c0, 0.0f);
    wmma::fill_fragment(c1, 0.0f);

    for (int k = 0; k < 128; k += 8) {
        wmma::fragment<wmma::matrix_a, 16, 16, 8, wmma::precision::tf32, wmma::row_major> a;
        wmma::load_matrix_sync(a, As + wm * 16 * 128 + k, 128);
        #pragma unroll
        for (int t = 0; t < a.num_elements; t++) a.x[t] = wmma::__float_to_tf32(a.x[t]);

        wmma::fragment<wmma::matrix_b, 16, 16, 8, wmma::precision::tf32, wmma::row_major> b;
        wmma::load_matrix_sync(b, Bs + k * 64 + wn * 32, 64);
        #pragma unroll
        for (int t = 0; t < b.num_elements; t++) b.x[t] = wmma::__float_to_tf32(b.x[t]);
        wmma::mma_sync(c0, a, b, c0);

        wmma::load_matrix_sync(b, Bs + k * 64 + wn * 32 + 16, 64);
        #pragma unroll
        for (int t = 0; t < b.num_elements; t++) b.x[t] = wmma::__float_to_tf32(b.x[t]);
        wmma::mma_sync(c1, a, b, c1);
    }
    wmma::store_matrix_sync(Cs + wm * 16 * 72 + wn * 32,      c0, 72, wmma::mem_row_major);
    wmma::store_matrix_sync(Cs + wm * 16 * 72 + wn * 32 + 16, c1, 72, wmma::mem_row_major);
    __syncthreads();

    // epilogue: bias + relu + run-length per-graph accumulation (batch is sorted)
    if (tid < 64) {
        const int col = col0 + tid;
        const float bias = __ldg(&b1[col]);
        int curg = -1;
        float run = 0.0f;
        for (int r = 0; r < 64; r++) {
            int node = row0 + r;
            if (node >= N_NODES) break;
            int g = bs[r];
            float val = fmaxf(Cs[r * 72 + tid] + bias, 0.0f);
            if (g != curg) {
                if (curg >= 0) atomicAdd(&g_gsum[curg * D_H + col], run);
                curg = g;
                run = val;
            } else {
                run += val;
            }
        }
        if (curg >= 0) atomicAdd(&g_gsum[curg * D_H + col], run);
    }
}

// pooled2[g,:] = (gsum[g,:]/cnt[g]) @ w2 + b2
__global__ void k_fc2(const float* __restrict__ w2, const float* __restrict__ b2) {
    __shared__ float s[D_H];
    int g = blockIdx.x;
    int j = threadIdx.x;  // 512
    float cnt = fmaxf((float)g_gcnt[g], 1.0f);
    s[j] = g_gsum[g * D_H + j] / cnt;
    __syncthreads();
    float acc = b2[j];
    #pragma unroll 8
    for (int k = 0; k < D_H; k++) acc += s[k] * __ldg(&w2[(size_t)k * D_H + j]);
    g_pool2[g * D_H + j] = acc;
}

// out[g,o] = pooled2[g,:] @ wc[:,o] + bc[o]
__global__ void k_fc3(const float* __restrict__ wc, const float* __restrict__ bc,
                      float* __restrict__ out) {
    int tid = threadIdx.x;  // 1024 = 64*16
    int g = tid >> 4, o = tid & 15;
    const float* p = g_pool2 + g * D_H;
    float acc = bc[o];
    #pragma unroll 8
    for (int j = 0; j < D_H; j++) acc += p[j] * __ldg(&wc[j * D_OUT + o]);
    out[g * D_OUT + o] = acc;
}

// ---------------- launch ----------------
extern "C" void kernel_launch(void* const* d_in, const int* in_sizes, int n_in,
                              void* d_out, int out_size) {
    const float* x     = (const float*)d_in[0];
    const int*   ei    = (const int*)d_in[1];   // [2, E] (jax canonicalizes int64->int32)
    const int*   batch = (const int*)d_in[2];
    const float* w1    = (const float*)d_in[3];
    const float* b1    = (const float*)d_in[4];
    const float* w2    = (const float*)d_in[5];
    const float* b2    = (const float*)d_in[6];
    const float* wc    = (const float*)d_in[7];
    const float* bc    = (const float*)d_in[8];

    const int* rows = ei;
    const int* cols = ei + N_EDGES;

    float *s1, *s2, *invdeg;
    cudaGetSymbolAddress((void**)&s1, g_s1);
    cudaGetSymbolAddress((void**)&s2, g_s2);
    cudaGetSymbolAddress((void**)&invdeg, g_invdeg);

    cudaFuncSetAttribute(k_gemm_pool, cudaFuncAttributeMaxDynamicSharedMemorySize,
                         GEMM_SMEM_BYTES);

    k_zero<<<(N_NODES + 255) / 256, 256>>>();
    k_deg<<<(N_EDGES + 255) / 256, 256>>>(rows);
    k_invdeg<<<(N_NODES + 255) / 256, 256>>>();
    k_hist<<<64, 256>>>(batch);

    const int prep_blocks = (N_NODES * (D_IN / 4) + 255) / 256;
    const int scat_blocks = (N_EDGES + 7) / 8;

    // hop 1: a1 = (I+A) x            (h0 = x, scale = 1)
    k_prep<<<prep_blocks, 256>>>((float4*)s1, (const float4*)x, nullptr);
    k_scatter<<<scat_blocks, 256>>>(s1, x, nullptr, rows, cols);
    // hop 2: a2 = (I+A) (invdeg .* a1)
    k_prep<<<prep_blocks, 256>>>((float4*)s2, (const float4*)s1, invdeg);
    k_scatter<<<scat_blocks, 256>>>(s2, s1, invdeg, rows, cols);
    // hop 3: a3 = (I+A) (invdeg .* a2)   (into s1, s1 is free now)
    k_prep<<<prep_blocks, 256>>>((float4*)s1, (const float4*)s2, invdeg);
    k_scatter<<<scat_blocks, 256>>>(s1, s2, invdeg, rows, cols);

    // fused GEMM (h3 = invdeg .* a3): relu(h3@w1+b1) + per-graph pooling sums
    dim3 ggrid((N_NODES + 63) / 64, D_H / 64);
    k_gemm_pool<<<ggrid, 256, GEMM_SMEM_BYTES>>>(s1, invdeg, w1, b1, batch);

    // tiny tail: pooled@w2+b2, then @wc+bc
    k_fc2<<<N_GRAPHS, D_H>>>(w2, b2);
    k_fc3<<<1, N_GRAPHS * D_OUT>>>(wc, bc, (float*)d_out);
}

// round 2
// speedup vs baseline: 1.4943x; 1.4943x over previous
#include <cuda_runtime.h>
#include <mma.h>
#include <cstdint>

using namespace nvcuda;

// Problem constants (fixed shapes)
#define N_NODES  50000
#define N_EDGES  1600000
#define N_GRAPHS 64
#define D_IN     128
#define D_H      512
#define D_OUT    16

// ---------------- device scratch (no allocation allowed) ----------------
__device__ float g_s1[(size_t)N_NODES * D_IN];   // 25.6 MB
__device__ float g_s2[(size_t)N_NODES * D_IN];   // 25.6 MB
__device__ int   g_deg[N_NODES];
__device__ float g_invdeg[N_NODES];
__device__ int   g_off[N_NODES + 1];
__device__ int   g_cur[N_NODES];
__device__ int   g_csr[N_EDGES];                 // 6.4 MB
__device__ float g_gsum[N_GRAPHS * D_H];
__device__ int   g_gcnt[N_GRAPHS];
__device__ float g_pool2[N_GRAPHS * D_H];

// ---------------- kernels ----------------

__global__ void k_zero() {
    int i = blockIdx.x * blockDim.x + threadIdx.x;
    if (i < N_NODES) { g_deg[i] = 0; g_cur[i] = 0; }
    if (i < N_GRAPHS * D_H) g_gsum[i] = 0.0f;
    if (i < N_GRAPHS) g_gcnt[i] = 0;
}

__global__ void k_deg(const int* __restrict__ rows) {
    int e = blockIdx.x * blockDim.x + threadIdx.x;
    if (e < N_EDGES) atomicAdd(&g_deg[rows[e]], 1);
}

// single-block exclusive scan of deg -> off, plus invdeg
__global__ void __launch_bounds__(1024) k_scan() {
    const int C = (N_NODES + 1023) / 1024;  // 49
    int t = threadIdx.x;
    int start = t * C;
    int end = min(start + C, N_NODES);

    int sum = 0;
    for (int i = start; i < end; i++) sum += g_deg[i];

    __shared__ int part[1024];
    part[t] = sum;
    __syncthreads();
    for (int d = 1; d < 1024; d <<= 1) {
        int v = (t >= d) ? part[t - d] : 0;
        __syncthreads();
        part[t] += v;
        __syncthreads();
    }
    int run = (t == 0) ? 0 : part[t - 1];
    for (int i = start; i < end; i++) { g_off[i] = run; run += g_deg[i]; }
    if (end == N_NODES) g_off[N_NODES] = run;  // safe: all tail threads write total

    for (int i = t; i < N_NODES; i += 1024)
        g_invdeg[i] = 1.0f / (float)(g_deg[i] + 1);  // +1 self loop
}

__global__ void k_fill(const int* __restrict__ rows, const int* __restrict__ cols) {
    int e = blockIdx.x * blockDim.x + threadIdx.x;
    if (e >= N_EDGES) return;
    int r = __ldg(&rows[e]);
    int p = atomicAdd(&g_cur[r], 1);
    g_csr[g_off[r] + p] = __ldg(&cols[e]);
}

__global__ void k_hist(const int* __restrict__ batch) {
    __shared__ int h[N_GRAPHS];
    if (threadIdx.x < N_GRAPHS) h[threadIdx.x] = 0;
    __syncthreads();
    for (int i = blockIdx.x * blockDim.x + threadIdx.x; i < N_NODES;
         i += gridDim.x * blockDim.x)
        atomicAdd(&h[batch[i]], 1);
    __syncthreads();
    if (threadIdx.x < N_GRAPHS) atomicAdd(&g_gcnt[threadIdx.x], h[threadIdx.x]);
}

// one warp per node: dst[r] = invdeg[r] * (src[r] + sum_{c in N(r)} src[c])
__global__ void __launch_bounds__(256) k_hop(const float4* __restrict__ src,
                                             float4* __restrict__ dst) {
    int r = (blockIdx.x * blockDim.x + threadIdx.x) >> 5;
    if (r >= N_NODES) return;
    int lane = threadIdx.x & 31;

    int js = __ldg(&g_off[r]);
    int je = __ldg(&g_off[r + 1]);

    float4 acc = __ldg(src + (size_t)r * 32 + lane);  // self loop

    int j = js;
    for (; j + 4 <= je; j += 4) {
        int c0 = __ldg(&g_csr[j + 0]);
        int c1 = __ldg(&g_csr[j + 1]);
        int c2 = __ldg(&g_csr[j + 2]);
        int c3 = __ldg(&g_csr[j + 3]);
        float4 v0 = __ldg(src + (size_t)c0 * 32 + lane);
        float4 v1 = __ldg(src + (size_t)c1 * 32 + lane);
        float4 v2 = __ldg(src + (size_t)c2 * 32 + lane);
        float4 v3 = __ldg(src + (size_t)c3 * 32 + lane);
        acc.x += (v0.x + v1.x) + (v2.x + v3.x);
        acc.y += (v0.y + v1.y) + (v2.y + v3.y);
        acc.z += (v0.z + v1.z) + (v2.z + v3.z);
        acc.w += (v0.w + v1.w) + (v2.w + v3.w);
    }
    for (; j < je; j++) {
        int c = __ldg(&g_csr[j]);
        float4 v = __ldg(src + (size_t)c * 32 + lane);
        acc.x += v.x; acc.y += v.y; acc.z += v.z; acc.w += v.w;
    }
    float s = __ldg(&g_invdeg[r]);
    acc.x *= s; acc.y *= s; acc.z *= s; acc.w *= s;
    dst[(size_t)r * 32 + lane] = acc;
}

// C = relu( A @ w1 + b1 ), fused per-graph sum accumulation.
// Block tile: 64(M) x 64(N), K=128 fully resident in SMEM. tf32 wmma.
#define GEMM_SMEM_BYTES ((64 * 128 + 128 * 64 + 64 * 72 + 64) * 4)

__global__ void __launch_bounds__(256)
k_gemm_pool(const float* __restrict__ A,
            const float* __restrict__ w1, const float* __restrict__ b1,
            const int* __restrict__ batch) {
    extern __shared__ float sm[];
    float* As = sm;                 // [64][128]
    float* Bs = As + 64 * 128;      // [128][64]
    float* Cs = Bs + 128 * 64;      // [64][72]
    int*   bs = (int*)(Cs + 64 * 72);

    const int row0 = blockIdx.x * 64;
    const int col0 = blockIdx.y * 64;
    const int tid  = threadIdx.x;

    // load A tile, zero-pad beyond N_NODES
    for (int i = tid; i < 64 * 32; i += 256) {  // float4 index
        int r = i >> 5;
        int node = row0 + r;
        float4 v = make_float4(0.f, 0.f, 0.f, 0.f);
        if (node < N_NODES)
            v = __ldg(((const float4*)A) + (size_t)row0 * 32 + i);
        ((float4*)As)[i] = v;
    }
    // load B tile: w1[128][512] cols [col0, col0+64)
    for (int i = tid; i < 128 * 16; i += 256) {  // float4 index
        int r = i >> 4, q = i & 15;
        ((float4*)Bs)[i] = __ldg(((const float4*)(w1 + (size_t)r * D_H + col0)) + q);
    }
    if (tid < 64) {
        int node = row0 + tid;
        bs[tid] = (node < N_NODES) ? __ldg(&batch[node]) : -1;
    }
    __syncthreads();

    const int wid = tid >> 5;
    const int wm = wid & 3;    // row subtile 16*wm
    const int wn = wid >> 2;   // col slab 32*wn
    wmma::fragment<wmma::accumulator, 16, 16, 8, float> c0, c1;
    wmma::fill_fragment(c0, 0.0f);
    wmma::fill_fragment(c1, 0.0f);

    for (int k = 0; k < 128; k += 8) {
        wmma::fragment<wmma::matrix_a, 16, 16, 8, wmma::precision::tf32, wmma::row_major> a;
        wmma::load_matrix_sync(a, As + wm * 16 * 128 + k, 128);
        #pragma unroll
        for (int t = 0; t < a.num_elements; t++) a.x[t] = wmma::__float_to_tf32(a.x[t]);

        wmma::fragment<wmma::matrix_b, 16, 16, 8, wmma::precision::tf32, wmma::row_major> b;
        wmma::load_matrix_sync(b, Bs + k * 64 + wn * 32, 64);
        #pragma unroll
        for (int t = 0; t < b.num_elements; t++) b.x[t] = wmma::__float_to_tf32(b.x[t]);
        wmma::mma_sync(c0, a, b, c0);

        wmma::load_matrix_sync(b, Bs + k * 64 + wn * 32 + 16, 64);
        #pragma unroll
        for (int t = 0; t < b.num_elements; t++) b.x[t] = wmma::__float_to_tf32(b.x[t]);
        wmma::mma_sync(c1, a, b, c1);
    }
    wmma::store_matrix_sync(Cs + wm * 16 * 72 + wn * 32,      c0, 72, wmma::mem_row_major);
    wmma::store_matrix_sync(Cs + wm * 16 * 72 + wn * 32 + 16, c1, 72, wmma::mem_row_major);
    __syncthreads();

    // epilogue: bias + relu + run-length per-graph accumulation (batch is sorted)
    if (tid < 64) {
        const int col = col0 + tid;
        const float bias = __ldg(&b1[col]);
        int curg = -1;
        float run = 0.0f;
        for (int r = 0; r < 64; r++) {
            int node = row0 + r;
            if (node >= N_NODES) break;
            int g = bs[r];
            float val = fmaxf(Cs[r * 72 + tid] + bias, 0.0f);
            if (g != curg) {
                if (curg >= 0) atomicAdd(&g_gsum[curg * D_H + col], run);
                curg = g;
                run = val;
            } else {
                run += val;
            }
        }
        if (curg >= 0) atomicAdd(&g_gsum[curg * D_H + col], run);
    }
}

// pooled2[g,:] = (gsum[g,:]/cnt[g]) @ w2 + b2
__global__ void k_fc2(const float* __restrict__ w2, const float* __restrict__ b2) {
    __shared__ float s[D_H];
    int g = blockIdx.x;
    int j = threadIdx.x;  // 512
    float cnt = fmaxf((float)g_gcnt[g], 1.0f);
    s[j] = g_gsum[g * D_H + j] / cnt;
    __syncthreads();
    float acc = b2[j];
    #pragma unroll 8
    for (int k = 0; k < D_H; k++) acc += s[k] * __ldg(&w2[(size_t)k * D_H + j]);
    g_pool2[g * D_H + j] = acc;
}

// out[g,o] = pooled2[g,:] @ wc[:,o] + bc[o]
__global__ void k_fc3(const float* __restrict__ wc, const float* __restrict__ bc,
                      float* __restrict__ out) {
    int tid = threadIdx.x;  // 1024 = 64*16
    int g = tid >> 4, o = tid & 15;
    const float* p = g_pool2 + g * D_H;
    float acc = bc[o];
    #pragma unroll 8
    for (int j = 0; j < D_H; j++) acc += p[j] * __ldg(&wc[j * D_OUT + o]);
    out[g * D_OUT + o] = acc;
}

// ---------------- launch ----------------
extern "C" void kernel_launch(void* const* d_in, const int* in_sizes, int n_in,
                              void* d_out, int out_size) {
    const float* x     = (const float*)d_in[0];
    const int*   ei    = (const int*)d_in[1];   // [2, E] (jax canonicalizes int64->int32)
    const int*   batch = (const int*)d_in[2];
    const float* w1    = (const float*)d_in[3];
    const float* b1    = (const float*)d_in[4];
    const float* w2    = (const float*)d_in[5];
    const float* b2    = (const float*)d_in[6];
    const float* wc    = (const float*)d_in[7];
    const float* bc    = (const float*)d_in[8];

    const int* rows = ei;
    const int* cols = ei + N_EDGES;

    float *s1, *s2;
    cudaGetSymbolAddress((void**)&s1, g_s1);
    cudaGetSymbolAddress((void**)&s2, g_s2);

    cudaFuncSetAttribute(k_gemm_pool, cudaFuncAttributeMaxDynamicSharedMemorySize,
                         GEMM_SMEM_BYTES);

    // graph prep (launches 0-4)
    k_zero<<<(N_NODES + 255) / 256, 256>>>();
    k_deg<<<(N_EDGES + 255) / 256, 256>>>(rows);
    k_scan<<<1, 1024>>>();
    k_fill<<<(N_EDGES + 255) / 256, 256>>>(rows, cols);
    k_hist<<<64, 256>>>(batch);

    // 3 hops, pull-gather, no atomics (launches 5-7; ncu -s 5 catches hop1)
    const int hop_blocks = (N_NODES * 32 + 255) / 256;
    k_hop<<<hop_blocks, 256>>>((const float4*)x, (float4*)s1);
    k_hop<<<hop_blocks, 256>>>((const float4*)s1, (float4*)s2);
    k_hop<<<hop_blocks, 256>>>((const float4*)s2, (float4*)s1);

    // fused GEMM: relu(h3@w1+b1) + per-graph pooling sums
    dim3 ggrid((N_NODES + 63) / 64, D_H / 64);
    k_gemm_pool<<<ggrid, 256, GEMM_SMEM_BYTES>>>(s1, w1, b1, batch);

    // tiny tail: pooled@w2+b2, then @wc+bc
    k_fc2<<<N_GRAPHS, D_H>>>(w2, b2);
    k_fc3<<<1, N_GRAPHS * D_OUT>>>(wc, bc, (float*)d_out);
}

// round 3
// speedup vs baseline: 1.6138x; 1.0800x over previous
#include <cuda_runtime.h>
#include <cuda_fp16.h>
#include <mma.h>
#include <cstdint>

using namespace nvcuda;

// Problem constants (fixed shapes)
#define N_NODES  50000
#define N_EDGES  1600000
#define N_GRAPHS 64
#define D_IN     128
#define D_H      512
#define D_OUT    16

// ---------------- device scratch (no allocation allowed) ----------------
__device__ __half g_h[3][(size_t)N_NODES * D_IN];  // 3 x 12.8 MB
__device__ int   g_deg[N_NODES];
__device__ float g_invdeg[N_NODES];
__device__ int   g_off[N_NODES + 1];
__device__ int   g_cur[N_NODES];
__device__ int   g_csr[N_EDGES];                   // 6.4 MB
__device__ float g_gsum[N_GRAPHS * D_H];
__device__ int   g_gcnt[N_GRAPHS];
__device__ float g_pool2[N_GRAPHS * D_H];

// ---------------- helpers ----------------
__device__ __forceinline__ float4 h4_to_f4(uint2 u) {
    __half2 a = *(__half2*)&u.x;
    __half2 b = *(__half2*)&u.y;
    float2 fa = __half22float2(a);
    float2 fb = __half22float2(b);
    return make_float4(fa.x, fa.y, fb.x, fb.y);
}

// ---------------- kernels ----------------

__global__ void k_zero() {
    int i = blockIdx.x * blockDim.x + threadIdx.x;
    if (i < N_NODES) { g_deg[i] = 0; g_cur[i] = 0; }
    if (i < N_GRAPHS * D_H) g_gsum[i] = 0.0f;
    if (i < N_GRAPHS) g_gcnt[i] = 0;
}

__global__ void k_deg(const int* __restrict__ rows) {
    int e = blockIdx.x * blockDim.x + threadIdx.x;
    if (e < N_EDGES) atomicAdd(&g_deg[rows[e]], 1);
}

// single-block exclusive scan of deg -> off, plus invdeg
__global__ void __launch_bounds__(1024) k_scan() {
    const int C = (N_NODES + 1023) / 1024;  // 49
    int t = threadIdx.x;
    int start = t * C;
    int end = min(start + C, N_NODES);

    int sum = 0;
    for (int i = start; i < end; i++) sum += g_deg[i];

    __shared__ int part[1024];
    part[t] = sum;
    __syncthreads();
    for (int d = 1; d < 1024; d <<= 1) {
        int v = (t >= d) ? part[t - d] : 0;
        __syncthreads();
        part[t] += v;
        __syncthreads();
    }
    int run = (t == 0) ? 0 : part[t - 1];
    for (int i = start; i < end; i++) { g_off[i] = run; run += g_deg[i]; }
    if (end == N_NODES) g_off[N_NODES] = run;

    for (int i = t; i < N_NODES; i += 1024)
        g_invdeg[i] = 1.0f / (float)(g_deg[i] + 1);  // +1 self loop
}

__global__ void k_fill(const int* __restrict__ rows, const int* __restrict__ cols) {
    int e = blockIdx.x * blockDim.x + threadIdx.x;
    if (e >= N_EDGES) return;
    int r = __ldg(&rows[e]);
    int p = atomicAdd(&g_cur[r], 1);
    g_csr[g_off[r] + p] = __ldg(&cols[e]);
}

__global__ void k_hist(const int* __restrict__ batch) {
    __shared__ int h[N_GRAPHS];
    if (threadIdx.x < N_GRAPHS) h[threadIdx.x] = 0;
    __syncthreads();
    for (int i = blockIdx.x * blockDim.x + threadIdx.x; i < N_NODES;
         i += gridDim.x * blockDim.x)
        atomicAdd(&h[batch[i]], 1);
    __syncthreads();
    if (threadIdx.x < N_GRAPHS) atomicAdd(&g_gcnt[threadIdx.x], h[threadIdx.x]);
}

// x (fp32) -> h0 (fp16)
__global__ void k_x2h(const float2* __restrict__ x, __half2* __restrict__ dst) {
    const int total = N_NODES * (D_IN / 2);
    for (int i = blockIdx.x * blockDim.x + threadIdx.x; i < total;
         i += gridDim.x * blockDim.x)
        dst[i] = __float22half2_rn(__ldg(&x[i]));
}

// one warp per node: dst[r] = half( invdeg[r] * (src[r] + sum_{c in N(r)} src[c]) )
// rows are 128 halves = 32 uint2; lane owns uint2 #lane (4 values).
__global__ void __launch_bounds__(256) k_hop(const __half* __restrict__ srcp,
                                             __half* __restrict__ dstp) {
    int r = (blockIdx.x * blockDim.x + threadIdx.x) >> 5;
    if (r >= N_NODES) return;
    int lane = threadIdx.x & 31;
    const uint2* src = (const uint2*)srcp;

    int js = __ldg(&g_off[r]);
    int je = __ldg(&g_off[r + 1]);

    float4 acc = h4_to_f4(__ldg(src + (size_t)r * 32 + lane));  // self loop

    int j = js;
    for (; j + 8 <= je; j += 8) {
        int c[8];
        uint2 v[8];
        #pragma unroll
        for (int t = 0; t < 8; t++) c[t] = __ldg(&g_csr[j + t]);
        #pragma unroll
        for (int t = 0; t < 8; t++) v[t] = __ldg(src + (size_t)c[t] * 32 + lane);
        #pragma unroll
        for (int t = 0; t < 8; t++) {
            float4 f = h4_to_f4(v[t]);
            acc.x += f.x; acc.y += f.y; acc.z += f.z; acc.w += f.w;
        }
    }
    for (; j < je; j++) {
        int c = __ldg(&g_csr[j]);
        float4 f = h4_to_f4(__ldg(src + (size_t)c * 32 + lane));
        acc.x += f.x; acc.y += f.y; acc.z += f.z; acc.w += f.w;
    }
    float s = __ldg(&g_invdeg[r]);
    acc.x *= s; acc.y *= s; acc.z *= s; acc.w *= s;

    __half2 lo = __float22half2_rn(make_float2(acc.x, acc.y));
    __half2 hi = __float22half2_rn(make_float2(acc.z, acc.w));
    uint2 out;
    out.x = *(unsigned*)&lo;
    out.y = *(unsigned*)&hi;
    ((uint2*)dstp)[(size_t)r * 32 + lane] = out;
}

// C = relu( A @ w1 + b1 ), fused per-graph sum accumulation.
// Block tile: 64(M) x 64(N), K=128 fully resident in SMEM. tf32 wmma. A is fp16.
#define GEMM_SMEM_BYTES ((64 * 128 + 128 * 64 + 64 * 72 + 64) * 4)

__global__ void __launch_bounds__(256)
k_gemm_pool(const __half* __restrict__ A,
            const float* __restrict__ w1, const float* __restrict__ b1,
            const int* __restrict__ batch) {
    extern __shared__ float sm[];
    float* As = sm;                 // [64][128]
    float* Bs = As + 64 * 128;      // [128][64]
    float* Cs = Bs + 128 * 64;      // [64][72]
    int*   bs = (int*)(Cs + 64 * 72);

    const int row0 = blockIdx.x * 64;
    const int col0 = blockIdx.y * 64;
    const int tid  = threadIdx.x;

    // load A tile (fp16 -> fp32), zero-pad beyond N_NODES
    for (int i = tid; i < 64 * 32; i += 256) {  // uint2 index (4 halves each)
        int r = i >> 5, q = i & 31;
        int node = row0 + r;
        float4 v = make_float4(0.f, 0.f, 0.f, 0.f);
        if (node < N_NODES)
            v = h4_to_f4(__ldg(((const uint2*)A) + (size_t)node * 32 + q));
        ((float4*)As)[i] = v;
    }
    // load B tile: w1[128][512] cols [col0, col0+64)
    for (int i = tid; i < 128 * 16; i += 256) {  // float4 index
        int r = i >> 4, q = i & 15;
        ((float4*)Bs)[i] = __ldg(((const float4*)(w1 + (size_t)r * D_H + col0)) + q);
    }
    if (tid < 64) {
        int node = row0 + tid;
        bs[tid] = (node < N_NODES) ? __ldg(&batch[node]) : -1;
    }
    __syncthreads();

    const int wid = tid >> 5;
    const int wm = wid & 3;    // row subtile 16*wm
    const int wn = wid >> 2;   // col slab 32*wn
    wmma::fragment<wmma::accumulator, 16, 16, 8, float> c0, c1;
    wmma::fill_fragment(c0, 0.0f);
    wmma::fill_fragment(c1, 0.0f);

    for (int k = 0; k < 128; k += 8) {
        wmma::fragment<wmma::matrix_a, 16, 16, 8, wmma::precision::tf32, wmma::row_major> a;
        wmma::load_matrix_sync(a, As + wm * 16 * 128 + k, 128);
        #pragma unroll
        for (int t = 0; t < a.num_elements; t++) a.x[t] = wmma::__float_to_tf32(a.x[t]);

        wmma::fragment<wmma::matrix_b, 16, 16, 8, wmma::precision::tf32, wmma::row_major> b;
        wmma::load_matrix_sync(b, Bs + k * 64 + wn * 32, 64);
        #pragma unroll
        for (int t = 0; t < b.num_elements; t++) b.x[t] = wmma::__float_to_tf32(b.x[t]);
        wmma::mma_sync(c0, a, b, c0);

        wmma::load_matrix_sync(b, Bs + k * 64 + wn * 32 + 16, 64);
        #pragma unroll
        for (int t = 0; t < b.num_elements; t++) b.x[t] = wmma::__float_to_tf32(b.x[t]);
        wmma::mma_sync(c1, a, b, c1);
    }
    wmma::store_matrix_sync(Cs + wm * 16 * 72 + wn * 32,      c0, 72, wmma::mem_row_major);
    wmma::store_matrix_sync(Cs + wm * 16 * 72 + wn * 32 + 16, c1, 72, wmma::mem_row_major);
    __syncthreads();

    // epilogue: bias + relu + run-length per-graph accumulation (batch is sorted)
    if (tid < 64) {
        const int col = col0 + tid;
        const float bias = __ldg(&b1[col]);
        int curg = -1;
        float run = 0.0f;
        for (int r = 0; r < 64; r++) {
            int node = row0 + r;
            if (node >= N_NODES) break;
            int g = bs[r];
            float val = fmaxf(Cs[r * 72 + tid] + bias, 0.0f);
            if (g != curg) {
                if (curg >= 0) atomicAdd(&g_gsum[curg * D_H + col], run);
                curg = g;
                run = val;
            } else {
                run += val;
            }
        }
        if (curg >= 0) atomicAdd(&g_gsum[curg * D_H + col], run);
    }
}

// pooled2[g,:] = (gsum[g,:]/cnt[g]) @ w2 + b2
__global__ void k_fc2(const float* __restrict__ w2, const float* __restrict__ b2) {
    __shared__ float s[D_H];
    int g = blockIdx.x;
    int j = threadIdx.x;  // 512
    float cnt = fmaxf((float)g_gcnt[g], 1.0f);
    s[j] = g_gsum[g * D_H + j] / cnt;
    __syncthreads();
    float acc = b2[j];
    #pragma unroll 8
    for (int k = 0; k < D_H; k++) acc += s[k] * __ldg(&w2[(size_t)k * D_H + j]);
    g_pool2[g * D_H + j] = acc;
}

// out[g,o] = pooled2[g,:] @ wc[:,o] + bc[o]
__global__ void k_fc3(const float* __restrict__ wc, const float* __restrict__ bc,
                      float* __restrict__ out) {
    int tid = threadIdx.x;  // 1024 = 64*16
    int g = tid >> 4, o = tid & 15;
    const float* p = g_pool2 + g * D_H;
    float acc = bc[o];
    #pragma unroll 8
    for (int j = 0; j < D_H; j++) acc += p[j] * __ldg(&wc[j * D_OUT + o]);
    out[g * D_OUT + o] = acc;
}

// ---------------- launch ----------------
extern "C" void kernel_launch(void* const* d_in, const int* in_sizes, int n_in,
                              void* d_out, int out_size) {
    const float* x     = (const float*)d_in[0];
    const int*   ei    = (const int*)d_in[1];   // [2, E] (jax canonicalizes int64->int32)
    const int*   batch = (const int*)d_in[2];
    const float* w1    = (const float*)d_in[3];
    const float* b1    = (const float*)d_in[4];
    const float* w2    = (const float*)d_in[5];
    const float* b2    = (const float*)d_in[6];
    const float* wc    = (const float*)d_in[7];
    const float* bc    = (const float*)d_in[8];

    const int* rows = ei;
    const int* cols = ei + N_EDGES;

    __half *b0, *b1h, *b2h;
    cudaGetSymbolAddress((void**)&b0, g_h);
    b1h = b0 + (size_t)N_NODES * D_IN;
    b2h = b1h + (size_t)N_NODES * D_IN;

    cudaFuncSetAttribute(k_gemm_pool, cudaFuncAttributeMaxDynamicSharedMemorySize,
                         GEMM_SMEM_BYTES);

    // graph prep
    k_zero<<<(N_NODES + 255) / 256, 256>>>();
    k_deg<<<(N_EDGES + 255) / 256, 256>>>(rows);
    k_scan<<<1, 1024>>>();
    k_fill<<<(N_EDGES + 255) / 256, 256>>>(rows, cols);
    k_hist<<<64, 256>>>(batch);
    k_x2h<<<1024, 256>>>((const float2*)x, (__half2*)b0);

    // 3 hops, pull-gather fp16, no atomics
    const int hop_blocks = (N_NODES * 32 + 255) / 256;
    k_hop<<<hop_blocks, 256>>>(b0, b1h);
    k_hop<<<hop_blocks, 256>>>(b1h, b2h);
    k_hop<<<hop_blocks, 256>>>(b2h, b0);

    // fused GEMM: relu(h3@w1+b1) + per-graph pooling sums
    dim3 ggrid((N_NODES + 63) / 64, D_H / 64);
    k_gemm_pool<<<ggrid, 256, GEMM_SMEM_BYTES>>>(b0, w1, b1, batch);

    // tiny tail: pooled@w2+b2, then @wc+bc
    k_fc2<<<N_GRAPHS, D_H>>>(w2, b2);
    k_fc3<<<1, N_GRAPHS * D_OUT>>>(wc, bc, (float*)d_out);
}

// round 4
// speedup vs baseline: 2.0524x; 1.2718x over previous
#include <cuda_runtime.h>
#include <cuda_fp16.h>
#include <mma.h>
#include <cstdint>

using namespace nvcuda;

// Problem constants (fixed shapes)
#define N_NODES  50000
#define N_EDGES  1600000
#define N_GRAPHS 64
#define D_IN     128
#define D_H      512
#define D_OUT    16

// ---------------- device scratch (no allocation allowed) ----------------
__device__ __half g_h[3][(size_t)N_NODES * D_IN];  // 3 x 12.8 MB
__device__ __half g_w1h[D_IN * D_H];               // 128 KB
__device__ int   g_deg[N_NODES];
__device__ float g_invdeg[N_NODES];
__device__ int   g_off[N_NODES + 1];
__device__ int   g_cur[N_NODES];
__device__ int   g_csr[N_EDGES];                   // 6.4 MB
__device__ float g_gsum[N_GRAPHS * D_H];
__device__ int   g_gcnt[N_GRAPHS];
__device__ float g_pool2[N_GRAPHS * D_H];

// ---------------- helpers ----------------
__device__ __forceinline__ float4 h4_to_f4(uint2 u) {
    __half2 a = *(__half2*)&u.x;
    __half2 b = *(__half2*)&u.y;
    float2 fa = __half22float2(a);
    float2 fb = __half22float2(b);
    return make_float4(fa.x, fa.y, fb.x, fb.y);
}

// ---------------- kernels ----------------

__global__ void k_zero() {
    int i = blockIdx.x * blockDim.x + threadIdx.x;
    if (i < N_NODES) { g_deg[i] = 0; g_cur[i] = 0; }
    if (i < N_GRAPHS * D_H) g_gsum[i] = 0.0f;
    if (i < N_GRAPHS) g_gcnt[i] = 0;
}

__global__ void k_deg(const int* __restrict__ rows) {
    int e = blockIdx.x * blockDim.x + threadIdx.x;
    if (e < N_EDGES) atomicAdd(&g_deg[rows[e]], 1);
}

// single-block exclusive scan of deg -> off, plus invdeg
__global__ void __launch_bounds__(1024) k_scan() {
    const int C = (N_NODES + 1023) / 1024;  // 49
    int t = threadIdx.x;
    int start = t * C;
    int end = min(start + C, N_NODES);

    int sum = 0;
    for (int i = start; i < end; i++) sum += g_deg[i];

    __shared__ int part[1024];
    part[t] = sum;
    __syncthreads();
    for (int d = 1; d < 1024; d <<= 1) {
        int v = (t >= d) ? part[t - d] : 0;
        __syncthreads();
        part[t] += v;
        __syncthreads();
    }
    int run = (t == 0) ? 0 : part[t - 1];
    for (int i = start; i < end; i++) { g_off[i] = run; run += g_deg[i]; }
    if (end == N_NODES) g_off[N_NODES] = run;

    for (int i = t; i < N_NODES; i += 1024)
        g_invdeg[i] = 1.0f / (float)(g_deg[i] + 1);  // +1 self loop
}

__global__ void k_fill(const int* __restrict__ rows, const int* __restrict__ cols) {
    int e = blockIdx.x * blockDim.x + threadIdx.x;
    if (e >= N_EDGES) return;
    int r = __ldg(&rows[e]);
    int p = atomicAdd(&g_cur[r], 1);
    g_csr[g_off[r] + p] = __ldg(&cols[e]);
}

__global__ void k_hist(const int* __restrict__ batch) {
    __shared__ int h[N_GRAPHS];
    if (threadIdx.x < N_GRAPHS) h[threadIdx.x] = 0;
    __syncthreads();
    for (int i = blockIdx.x * blockDim.x + threadIdx.x; i < N_NODES;
         i += gridDim.x * blockDim.x)
        atomicAdd(&h[batch[i]], 1);
    __syncthreads();
    if (threadIdx.x < N_GRAPHS) atomicAdd(&g_gcnt[threadIdx.x], h[threadIdx.x]);
}

// x (fp32) -> h0 (fp16)
__global__ void k_x2h(const float2* __restrict__ x, __half2* __restrict__ dst) {
    const int total = N_NODES * (D_IN / 2);
    for (int i = blockIdx.x * blockDim.x + threadIdx.x; i < total;
         i += gridDim.x * blockDim.x)
        dst[i] = __float22half2_rn(__ldg(&x[i]));
}

// w1 (fp32) -> fp16
__global__ void k_w1h(const float2* __restrict__ w1) {
    int i = blockIdx.x * blockDim.x + threadIdx.x;
    if (i < D_IN * D_H / 2)
        ((__half2*)g_w1h)[i] = __float22half2_rn(__ldg(&w1[i]));
}

// one warp per node: dst[r] = half( invdeg[r] * (src[r] + sum_{c in N(r)} src[c]) )
// rows are 128 halves = 32 uint2; lane owns uint2 #lane (4 values).
__global__ void __launch_bounds__(256) k_hop(const __half* __restrict__ srcp,
                                             __half* __restrict__ dstp) {
    int r = (blockIdx.x * blockDim.x + threadIdx.x) >> 5;
    if (r >= N_NODES) return;
    int lane = threadIdx.x & 31;
    const uint2* src = (const uint2*)srcp;

    int js = __ldg(&g_off[r]);
    int je = __ldg(&g_off[r + 1]);

    float4 acc = h4_to_f4(__ldg(src + (size_t)r * 32 + lane));  // self loop

    int j = js;
    for (; j + 16 <= je; j += 16) {
        int c[16];
        #pragma unroll
        for (int t = 0; t < 16; t++) c[t] = __ldg(&g_csr[j + t]);
        uint2 v[16];
        #pragma unroll
        for (int t = 0; t < 16; t++) v[t] = __ldg(src + (size_t)c[t] * 32 + lane);
        #pragma unroll
        for (int t = 0; t < 16; t++) {
            float4 f = h4_to_f4(v[t]);
            acc.x += f.x; acc.y += f.y; acc.z += f.z; acc.w += f.w;
        }
    }
    for (; j + 4 <= je; j += 4) {
        int c[4];
        #pragma unroll
        for (int t = 0; t < 4; t++) c[t] = __ldg(&g_csr[j + t]);
        uint2 v[4];
        #pragma unroll
        for (int t = 0; t < 4; t++) v[t] = __ldg(src + (size_t)c[t] * 32 + lane);
        #pragma unroll
        for (int t = 0; t < 4; t++) {
            float4 f = h4_to_f4(v[t]);
            acc.x += f.x; acc.y += f.y; acc.z += f.z; acc.w += f.w;
        }
    }
    for (; j < je; j++) {
        int c = __ldg(&g_csr[j]);
        float4 f = h4_to_f4(__ldg(src + (size_t)c * 32 + lane));
        acc.x += f.x; acc.y += f.y; acc.z += f.z; acc.w += f.w;
    }
    float s = __ldg(&g_invdeg[r]);
    acc.x *= s; acc.y *= s; acc.z *= s; acc.w *= s;

    __half2 lo = __float22half2_rn(make_float2(acc.x, acc.y));
    __half2 hi = __float22half2_rn(make_float2(acc.z, acc.w));
    uint2 out;
    out.x = *(unsigned*)&lo;
    out.y = *(unsigned*)&hi;
    ((uint2*)dstp)[(size_t)r * 32 + lane] = out;
}

// C = relu( A @ w1 + b1 ), fused per-graph sum accumulation.
// Block tile: 64(M) x 64(N), K=128 resident in SMEM. fp16 HMMA, fp32 accum.
#define GEMM_SMEM_BYTES (64 * 128 * 2 + 128 * 64 * 2 + 64 * 72 * 4 + 64 * 4)

__global__ void __launch_bounds__(256)
k_gemm_pool(const __half* __restrict__ A,
            const float* __restrict__ b1, const int* __restrict__ batch) {
    extern __shared__ char smc[];
    __half* As = (__half*)smc;                    // [64][128]
    __half* Bs = As + 64 * 128;                   // [128][64]
    float*  Cs = (float*)(Bs + 128 * 64);         // [64][72]
    int*    bs = (int*)(Cs + 64 * 72);

    const int row0 = blockIdx.x * 64;
    const int col0 = blockIdx.y * 64;
    const int tid  = threadIdx.x;

    // load A tile (fp16, uint4 = 8 halves), zero-pad beyond N_NODES
    for (int i = tid; i < 64 * 16; i += 256) {
        int r = i >> 4, q = i & 15;
        int node = row0 + r;
        uint4 v = make_uint4(0u, 0u, 0u, 0u);
        if (node < N_NODES)
            v = __ldg(((const uint4*)A) + (size_t)node * 16 + q);
        ((uint4*)As)[i] = v;
    }
    // load B tile: w1h[128][512] cols [col0, col0+64)
    for (int i = tid; i < 128 * 8; i += 256) {
        int r = i >> 3, q = i & 7;
        ((uint4*)Bs)[i] = __ldg(((const uint4*)(g_w1h + (size_t)r * D_H + col0)) + q);
    }
    if (tid < 64) {
        int node = row0 + tid;
        bs[tid] = (node < N_NODES) ? __ldg(&batch[node]) : -1;
    }
    __syncthreads();

    const int wid = tid >> 5;
    const int wm = wid & 3;    // row subtile 16*wm
    const int wn = wid >> 2;   // col slab 32*wn
    wmma::fragment<wmma::accumulator, 16, 16, 16, float> c0, c1;
    wmma::fill_fragment(c0, 0.0f);
    wmma::fill_fragment(c1, 0.0f);

    #pragma unroll
    for (int k = 0; k < 128; k += 16) {
        wmma::fragment<wmma::matrix_a, 16, 16, 16, __half, wmma::row_major> a;
        wmma::load_matrix_sync(a, As + wm * 16 * 128 + k, 128);
        wmma::fragment<wmma::matrix_b, 16, 16, 16, __half, wmma::row_major> b;
        wmma::load_matrix_sync(b, Bs + k * 64 + wn * 32, 64);
        wmma::mma_sync(c0, a, b, c0);
        wmma::load_matrix_sync(b, Bs + k * 64 + wn * 32 + 16, 64);
        wmma::mma_sync(c1, a, b, c1);
    }
    wmma::store_matrix_sync(Cs + wm * 16 * 72 + wn * 32,      c0, 72, wmma::mem_row_major);
    wmma::store_matrix_sync(Cs + wm * 16 * 72 + wn * 32 + 16, c1, 72, wmma::mem_row_major);
    __syncthreads();

    // epilogue: bias + relu + run-length per-graph accumulation (batch sorted).
    // 256 threads = 64 cols x 4 row-strips of 16 rows.
    {
        const int col = tid & 63;
        const int q   = tid >> 6;           // strip 0..3
        const int gcol = col0 + col;
        const float bias = __ldg(&b1[gcol]);
        int curg = -1;
        float run = 0.0f;
        #pragma unroll 4
        for (int rr = 0; rr < 16; rr++) {
            int r = q * 16 + rr;
            if (row0 + r >= N_NODES) break;
            int g = bs[r];
            float val = fmaxf(Cs[r * 72 + col] + bias, 0.0f);
            if (g != curg) {
                if (curg >= 0) atomicAdd(&g_gsum[curg * D_H + gcol], run);
                curg = g;
                run = val;
            } else {
                run += val;
            }
        }
        if (curg >= 0) atomicAdd(&g_gsum[curg * D_H + gcol], run);
    }
}

// pooled2[g,:] = (gsum[g,:]/cnt[g]) @ w2 + b2
__global__ void k_fc2(const float* __restrict__ w2, const float* __restrict__ b2) {
    __shared__ float s[D_H];
    int g = blockIdx.x;
    int j = threadIdx.x;  // 512
    float cnt = fmaxf((float)g_gcnt[g], 1.0f);
    s[j] = g_gsum[g * D_H + j] / cnt;
    __syncthreads();
    float acc = b2[j];
    #pragma unroll 8
    for (int k = 0; k < D_H; k++) acc += s[k] * __ldg(&w2[(size_t)k * D_H + j]);
    g_pool2[g * D_H + j] = acc;
}

// out[g,o] = pooled2[g,:] @ wc[:,o] + bc[o]
__global__ void k_fc3(const float* __restrict__ wc, const float* __restrict__ bc,
                      float* __restrict__ out) {
    int tid = threadIdx.x;  // 1024 = 64*16
    int g = tid >> 4, o = tid & 15;
    const float* p = g_pool2 + g * D_H;
    float acc = bc[o];
    #pragma unroll 8
    for (int j = 0; j < D_H; j++) acc += p[j] * __ldg(&wc[j * D_OUT + o]);
    out[g * D_OUT + o] = acc;
}

// ---------------- launch ----------------
extern "C" void kernel_launch(void* const* d_in, const int* in_sizes, int n_in,
                              void* d_out, int out_size) {
    const float* x     = (const float*)d_in[0];
    const int*   ei    = (const int*)d_in[1];   // [2, E]
    const int*   batch = (const int*)d_in[2];
    const float* w1    = (const float*)d_in[3];
    const float* b1    = (const float*)d_in[4];
    const float* w2    = (const float*)d_in[5];
    const float* b2    = (const float*)d_in[6];
    const float* wc    = (const float*)d_in[7];
    const float* bc    = (const float*)d_in[8];

    const int* rows = ei;
    const int* cols = ei + N_EDGES;

    __half *b0, *b1h, *b2h;
    cudaGetSymbolAddress((void**)&b0, g_h);
    b1h = b0 + (size_t)N_NODES * D_IN;
    b2h = b1h + (size_t)N_NODES * D_IN;

    cudaFuncSetAttribute(k_gemm_pool, cudaFuncAttributeMaxDynamicSharedMemorySize,
                         GEMM_SMEM_BYTES);

    // graph prep
    k_zero<<<(N_NODES + 255) / 256, 256>>>();
    k_deg<<<(N_EDGES + 255) / 256, 256>>>(rows);
    k_scan<<<1, 1024>>>();
    k_fill<<<(N_EDGES + 255) / 256, 256>>>(rows, cols);
    k_hist<<<64, 256>>>(batch);
    k_x2h<<<1024, 256>>>((const float2*)x, (__half2*)b0);
    k_w1h<<<(D_IN * D_H / 2 + 255) / 256, 256>>>((const float2*)w1);

    // 3 hops, pull-gather fp16, no atomics
    const int hop_blocks = (N_NODES * 32 + 255) / 256;
    k_hop<<<hop_blocks, 256>>>(b0, b1h);
    k_hop<<<hop_blocks, 256>>>(b1h, b2h);
    k_hop<<<hop_blocks, 256>>>(b2h, b0);

    // fused GEMM: relu(h3@w1+b1) + per-graph pooling sums (fp16 HMMA)
    dim3 ggrid((N_NODES + 63) / 64, D_H / 64);
    k_gemm_pool<<<ggrid, 256, GEMM_SMEM_BYTES>>>(b0, b1, batch);

    // tiny tail: pooled@w2+b2, then @wc+bc
    k_fc2<<<N_GRAPHS, D_H>>>(w2, b2);
    k_fc3<<<1, N_GRAPHS * D_OUT>>>(wc, bc, (float*)d_out);
}